// round 15
// baseline (speedup 1.0000x reference)
#include <cuda_runtime.h>
#include <cuda_fp16.h>
#include <cstdint>
#include <math.h>

#define BB   8
#define CC   256
#define TT   4096
#define KK   1024
#define NN   (BB*TT)
#define EPSF 1e-10f

#define ZQ_SIZE   (BB*CC*TT)
#define PROB_SIZE (NN*KK)
#define TOTAL_OUT (ZQ_SIZE + 1 + 2*PROB_SIZE + KK)

#define SROWS 8                       // rows per softmax block (32 KB smem)

// ---------------- device scratch (static — no runtime allocation) ----------
__device__ float    g_bnorm[KK];
__device__ float    g_mp_partial[(NN/SROWS) * KK];     // 16 MB
__device__ float    g_mp2[8 * KK];
__device__ float    g_logits[(size_t)NN * KK];         // 128 MB
__device__ uint32_t g_enc_hi[(size_t)NN * KK / 2];     // 64 MB (fp16x2, [n][512w])
__device__ float    g_rinv[NN];
__device__ uint32_t g_book_hi[KK * CC / 2];            // fp16x2 words, [k][128w]
__device__ uint32_t g_book_lo[KK * CC / 2];
__device__ uint32_t g_bookT_hi[CC * KK / 2];           // fp16x2 words, [c][512w]

// ---------------- helpers ---------------------------------------------------
__device__ __forceinline__ uint32_t smem_u32(const void* p) {
    uint32_t a;
    asm("{ .reg .u64 t; cvta.to.shared.u64 t, %1; cvt.u32.u64 %0, t; }"
        : "=r"(a) : "l"(p));
    return a;
}
__device__ __forceinline__ void cp16(uint32_t dst, size_t gsrc) {
    asm volatile("cp.async.cg.shared.global [%0], [%1], 16;" :: "r"(dst), "l"(gsrc));
}
#define CP_COMMIT()  asm volatile("cp.async.commit_group;" ::: "memory")
#define CP_WAIT(N)   asm volatile("cp.async.wait_group %0;" :: "n"(N) : "memory")

__device__ __forceinline__ void ldsm4(uint32_t* r, uint32_t addr) {
    asm volatile("ldmatrix.sync.aligned.m8n8.x4.shared.b16 {%0,%1,%2,%3}, [%4];"
        : "=r"(r[0]), "=r"(r[1]), "=r"(r[2]), "=r"(r[3]) : "r"(addr));
}
__device__ __forceinline__ void mma_f16(float* d, const uint32_t* a,
                                        uint32_t b0, uint32_t b1) {
    asm volatile("mma.sync.aligned.m16n8k16.row.col.f32.f16.f16.f32 "
        "{%0,%1,%2,%3}, {%4,%5,%6,%7}, {%8,%9}, {%0,%1,%2,%3};"
        : "+f"(d[0]), "+f"(d[1]), "+f"(d[2]), "+f"(d[3])
        : "r"(a[0]), "r"(a[1]), "r"(a[2]), "r"(a[3]), "r"(b0), "r"(b1));
}
__device__ __forceinline__ uint32_t pack_h2(float a, float b) {
    __half2 t = __floats2half2_rn(a, b);
    return *reinterpret_cast<uint32_t*>(&t);
}
__device__ __forceinline__ float warp_max(float v) {
    #pragma unroll
    for (int o = 16; o > 0; o >>= 1) v = fmaxf(v, __shfl_xor_sync(0xffffffffu, v, o));
    return v;
}
__device__ __forceinline__ float warp_sum(float v) {
    #pragma unroll
    for (int o = 16; o > 0; o >>= 1) v += __shfl_xor_sync(0xffffffffu, v, o);
    return v;
}
__device__ __forceinline__ float gumbelf(float uu) {
    return -__logf(-__logf(uu + EPSF) + EPSF);
}

// ---------------------------------------------------------------------------
// Prep kernels
// ---------------------------------------------------------------------------
__global__ void bnorm_kernel(const float* __restrict__ book) {
    int gw = (blockIdx.x * blockDim.x + threadIdx.x) >> 5;
    int lane = threadIdx.x & 31;
    if (gw >= KK) return;
    const float* row = book + (size_t)gw * CC;
    float s = 0.f;
    #pragma unroll
    for (int c = lane; c < CC; c += 32) { float v = row[c]; s = fmaf(v, v, s); }
    s = warp_sum(s);
    if (lane == 0) g_bnorm[gw] = s;
}

__global__ void split_book(const float* __restrict__ book) {
    __half* bh  = reinterpret_cast<__half*>(g_book_hi);
    __half* bl  = reinterpret_cast<__half*>(g_book_lo);
    __half* bth = reinterpret_cast<__half*>(g_bookT_hi);
    int idx = blockIdx.x * 256 + threadIdx.x;
    for (int i = idx; i < KK * CC; i += 65536) {
        int k = i >> 8, c = i & 255;
        float v = book[i];
        __half h = __float2half(v);
        bh[i] = h;
        bl[i] = __float2half(v - __half2float(h));
        bth[c * KK + k] = h;
    }
}

// 2-stage deterministic mean_prob reduction (4096 partial blocks now)
__global__ void mp_reduce1() {
    int idx = blockIdx.x * 256 + threadIdx.x;     // 32 blocks -> 8192 threads
    int k = idx & 1023, c = idx >> 10;            // c in 0..7
    float s = 0.f;
    #pragma unroll 8
    for (int b = 0; b < (NN/SROWS)/8; ++b)
        s += g_mp_partial[(size_t)(c * ((NN/SROWS)/8) + b) * KK + k];
    g_mp2[c * KK + k] = s;
}
__global__ void mp_reduce2(float* __restrict__ mean_out) {
    int k = blockIdx.x * 256 + threadIdx.x;
    float s = 0.f;
    #pragma unroll
    for (int c = 0; c < 8; ++c) s += g_mp2[c * KK + k];
    mean_out[k] = s;
}

// ---------------------------------------------------------------------------
// GEMM1 (R10/R13 layout — measured fast): logits = (2*zhi.(bhi+blo) - |zhi|^2 - |b|^2)*pq
// |zhi|^2: per-row additive const -> cancels in all softmax-derived outputs.
// 256 blocks x 256 thr; block = 128 rows; book in 64-code chunks,
// cp.async double-buffered. Warp tile 32x32, ldsm:mma = 6:16.
// ---------------------------------------------------------------------------
#define G1_BBUF  72192
#define G1_BSZ   67584          // per buffer: Bh 33792 + Bl 33792
#define G1_SMEM  207360

__global__ __launch_bounds__(256, 1)
void gemm1(const float* __restrict__ z, const float* __restrict__ lpq) {
    extern __shared__ char smem[];
    float* zn = reinterpret_cast<float*>(smem);
    float* bn = reinterpret_cast<float*>(smem + 512);
    __half* Ah = reinterpret_cast<__half*>(smem + 4608);
    const uint32_t sb = smem_u32(smem);
    const uint32_t Ah_b = sb + 4608;

    const int tid = threadIdx.x, lane = tid & 31, wid = tid >> 5;
    const int blk = blockIdx.x;
    const int n0 = blk * 128;
    const int b  = blk >> 5;
    const int t0 = (blk & 31) * 128;

    const size_t gbh = __cvta_generic_to_global(g_book_hi);
    const size_t gbl = __cvta_generic_to_global(g_book_lo);

    auto fill_b = [&](int nt, int p) {
        const uint32_t dstb = sb + G1_BBUF + p * G1_BSZ;
        const size_t srcoff = (size_t)(nt * 64) * 512;   // 64 rows x 512 B
        #pragma unroll
        for (int j = 0; j < 8; ++j) {
            int i = j * 256 + tid;          // 0..2047
            int row = i >> 5, f4 = i & 31;
            uint32_t d = dstb + row * 528 + f4 * 16;
            size_t s = srcoff + (size_t)row * 512 + f4 * 16;
            cp16(d,         gbh + s);
            cp16(d + 33792, gbl + s);
        }
    };

    fill_b(0, 0);
    CP_COMMIT();

    for (int i = tid; i < KK; i += 256) bn[i] = g_bnorm[i];

    // ---- A fill (hi only): thread = channel c, rows = t ----
    {
        const float* zp = z + (size_t)b * CC * TT + (size_t)tid * TT + t0;
        #pragma unroll 4
        for (int i = 0; i < 32; ++i) {
            float4 v = *reinterpret_cast<const float4*>(zp + 4*i);
            Ah[(4*i+0)*264 + tid] = __float2half(v.x);
            Ah[(4*i+1)*264 + tid] = __float2half(v.y);
            Ah[(4*i+2)*264 + tid] = __float2half(v.z);
            Ah[(4*i+3)*264 + tid] = __float2half(v.w);
        }
    }
    __syncthreads();

    // ---- z row norms from fp16-hi (output-exact by softmax invariance) ----
    for (int rr = 0; rr < 16; ++rr) {
        int r = wid * 16 + rr;
        float s = 0.f;
        #pragma unroll
        for (int c = lane; c < CC; c += 32) {
            float v = __half2float(Ah[r*264 + c]);
            s = fmaf(v, v, s);
        }
        s = warp_sum(s);
        if (lane == 0) zn[r] = s;
    }

    const float pqv = 0.5f / (1.0f + expf(lpq[0]));

    const int wm = wid >> 1, wn = wid & 1;
    const int r0w = wm * 32, n0w = wn * 32;
    const int g = lane >> 2, tig = lane & 3;
    const int arow  = (lane & 7) + ((lane >> 3) & 1) * 8;
    const int akoff = (lane >> 4) * 8;
    const int brow  = (lane & 7) + (lane >> 4) * 8;
    const int bkoff = ((lane >> 3) & 1) * 8;

    for (int nt = 0; nt < 16; ++nt) {
        if (nt + 1 < 16) {
            fill_b(nt + 1, (nt + 1) & 1);
            CP_COMMIT();
            CP_WAIT(1);
        } else {
            CP_WAIT(0);
        }
        __syncthreads();

        const uint32_t Bh_b = sb + G1_BBUF + (nt & 1) * G1_BSZ;
        const uint32_t Bl_b = Bh_b + 33792;

        float acc[2][4][4];
        #pragma unroll
        for (int i = 0; i < 2; ++i)
            #pragma unroll
            for (int j = 0; j < 4; ++j)
                #pragma unroll
                for (int e = 0; e < 4; ++e) acc[i][j][e] = 0.f;

        #pragma unroll 2
        for (int ks = 0; ks < 16; ++ks) {
            uint32_t af[2][4], bf[2][4], blf[2][4];
            #pragma unroll
            for (int mt = 0; mt < 2; ++mt) {
                uint32_t off = (uint32_t)((r0w + mt*16 + arow) * 264 + ks*16 + akoff) * 2;
                ldsm4(af[mt], Ah_b + off);
            }
            #pragma unroll
            for (int np = 0; np < 2; ++np) {
                uint32_t off = (uint32_t)((n0w + np*16 + brow) * 264 + ks*16 + bkoff) * 2;
                ldsm4(bf[np],  Bh_b + off);
                ldsm4(blf[np], Bl_b + off);
            }
            #pragma unroll
            for (int mt = 0; mt < 2; ++mt)
                #pragma unroll
                for (int ntile = 0; ntile < 4; ++ntile) {
                    int np = ntile >> 1, sub = (ntile & 1) * 2;
                    mma_f16(acc[mt][ntile], af[mt], bf[np][sub],  bf[np][sub+1]);
                    mma_f16(acc[mt][ntile], af[mt], blf[np][sub], blf[np][sub+1]);
                }
        }

        // epilogue: scale + direct float2 stores to g_logits
        #pragma unroll
        for (int mt = 0; mt < 2; ++mt) {
            int r_lo = r0w + mt*16 + g;
            float zn0 = zn[r_lo], zn1 = zn[r_lo + 8];
            #pragma unroll
            for (int ntile = 0; ntile < 4; ++ntile) {
                int col = nt*64 + n0w + ntile*8 + 2*tig;
                float bn0 = bn[col], bn1 = bn[col + 1];
                float2 w0, w1;
                w0.x = (2.f*acc[mt][ntile][0] - zn0 - bn0) * pqv;
                w0.y = (2.f*acc[mt][ntile][1] - zn0 - bn1) * pqv;
                w1.x = (2.f*acc[mt][ntile][2] - zn1 - bn0) * pqv;
                w1.y = (2.f*acc[mt][ntile][3] - zn1 - bn1) * pqv;
                *reinterpret_cast<float2*>(&g_logits[(size_t)(n0 + r_lo) * KK + col]) = w0;
                *reinterpret_cast<float2*>(&g_logits[(size_t)(n0 + r_lo + 8) * KK + col]) = w1;
            }
        }
        __syncthreads();
    }
}

// ---------------------------------------------------------------------------
// Softmax kernel: prob/log_prob/mean partials + Gumbel-exp -> enc (fp16 hi)
// 4096 blocks x 256 thr; block = 8 rows; 32 KB smem + <=64 regs -> 4 CTAs/SM
// ---------------------------------------------------------------------------
#define SMB_TOT  (SROWS * KK + 8)

__global__ __launch_bounds__(256, 4)
void gvq_soft(const float* __restrict__ u, const float* __restrict__ lpq,
              float* __restrict__ prob_out, float* __restrict__ logp_out,
              float* __restrict__ pq_out, int full)
{
    extern __shared__ float sm[];
    float* L  = sm;
    float* ra = sm + SROWS * KK;

    const int tid = threadIdx.x, blk = blockIdx.x;
    const int n0 = blk * SROWS;
    const int lane = tid & 31, warp = tid >> 5;

    if (full && blk == 0 && tid == 0)
        *pq_out = 0.5f / (1.0f + expf(lpq[0]));

    #pragma unroll
    for (int it = 0; it < 8; ++it) {
        int idx = it * 256 + tid;
        int r = idx >> 8, kw = idx & 255;
        *reinterpret_cast<float4*>(&L[r * KK + kw * 4]) =
            *reinterpret_cast<const float4*>(&g_logits[(size_t)(n0 + r) * KK + kw * 4]);
    }
    __syncthreads();

    if (full) {
        // warp w handles row w (8 warps, 8 rows)
        {
            int r = warp;
            const float* Lr = L + r * KK;
            float m = __int_as_float(0xff800000);
            #pragma unroll
            for (int kb = 0; kb < 8; ++kb) {
                float4 v = *reinterpret_cast<const float4*>(Lr + kb*128 + lane*4);
                m = fmaxf(m, fmaxf(fmaxf(v.x, v.y), fmaxf(v.z, v.w)));
            }
            m = warp_max(m);
            float s = 0.f;
            #pragma unroll
            for (int kb = 0; kb < 8; ++kb) {
                float4 v = *reinterpret_cast<const float4*>(Lr + kb*128 + lane*4);
                s += __expf(v.x - m) + __expf(v.y - m) + __expf(v.z - m) + __expf(v.w - m);
            }
            s = warp_sum(s);
            if (lane == 0) ra[r] = m + __logf(s);
        }
        __syncthreads();

        const float invN = 1.0f / (float)NN;
        #pragma unroll
        for (int j = 0; j < 4; ++j) {
            int k = tid + j * 256;
            float mp = 0.f;
            #pragma unroll 8
            for (int r = 0; r < SROWS; ++r) {
                float lp = L[r * KK + k] - ra[r];
                float p  = __expf(lp);
                prob_out[(size_t)(n0 + r) * KK + k] = p;
                logp_out[(size_t)(n0 + r) * KK + k] = lp;
                mp += p;
            }
            g_mp_partial[(size_t)blk * KK + k] = mp * invN;
        }
        __syncthreads();
    }

    // Gumbel + temperature-0.5 softmax; emit unnormalized exp as fp16 (hi only)
    {
        int r = warp;
        const float* ur = u + (size_t)(n0 + r) * KK;
        float* Lr = L + r * KK;
        float m = __int_as_float(0xff800000);
        #pragma unroll
        for (int kb = 0; kb < 8; ++kb) {
            float4 uv = *reinterpret_cast<const float4*>(ur + kb*128 + lane*4);
            float4 lv = *reinterpret_cast<float4*>(Lr + kb*128 + lane*4);
            lv.x += gumbelf(uv.x); lv.y += gumbelf(uv.y);
            lv.z += gumbelf(uv.z); lv.w += gumbelf(uv.w);
            *reinterpret_cast<float4*>(Lr + kb*128 + lane*4) = lv;
            m = fmaxf(m, fmaxf(fmaxf(lv.x, lv.y), fmaxf(lv.z, lv.w)));
        }
        m = warp_max(m);
        float s = 0.f;
        #pragma unroll
        for (int kb = 0; kb < 8; ++kb) {
            float4 lv = *reinterpret_cast<float4*>(Lr + kb*128 + lane*4);
            float e0 = __expf(2.0f * (lv.x - m));
            float e1 = __expf(2.0f * (lv.y - m));
            float e2 = __expf(2.0f * (lv.z - m));
            float e3 = __expf(2.0f * (lv.w - m));
            s += e0 + e1 + e2 + e3;
            uint2 hv;
            hv.x = pack_h2(e0, e1);
            hv.y = pack_h2(e2, e3);
            reinterpret_cast<uint2*>(g_enc_hi)[(size_t)(n0 + r) * 256 + kb * 32 + lane] = hv;
        }
        s = warp_sum(s);
        if (lane == 0) g_rinv[n0 + r] = 1.0f / s;
    }
}

// ---------------------------------------------------------------------------
// GEMM2: z_q = (ehi @ bhi) * rinv  (fp16 1-term), cp.async double-buffer
// 512 blocks: blk>>1 = 128-row tile, blk&1 = 128-c half. k streamed in 64s.
// ---------------------------------------------------------------------------
#define G2_BUF   512
#define G2_BSZ   36864
#define G2_SMEM  74240

__global__ __launch_bounds__(256, 2)
void gemm2(float* __restrict__ zq_out) {
    extern __shared__ char smem[];
    float* rinv_s = reinterpret_cast<float*>(smem);
    const uint32_t sb = smem_u32(smem);

    const int tid = threadIdx.x, lane = tid & 31, wid = tid >> 5;
    const int blk = blockIdx.x;
    const int rt = blk >> 1, ch = blk & 1;
    const int n0 = rt * 128;
    const int c0 = ch * 128;
    const int bb = rt >> 5;
    const int t0 = (rt & 31) * 128;

    const size_t geh = __cvta_generic_to_global(g_enc_hi);
    const size_t gth = __cvta_generic_to_global(g_bookT_hi);

    auto fill = [&](int kc, int p) {
        const uint32_t dstb = sb + G2_BUF + p * G2_BSZ;
        #pragma unroll
        for (int j = 0; j < 4; ++j) {
            int i = j * 256 + tid;           // 0..1023
            int row = i >> 3, f4 = i & 7;
            uint32_t d = dstb + row * 144 + f4 * 16;
            cp16(d,         geh + (size_t)(n0 + row) * 2048 + kc * 128 + f4 * 16);
            cp16(d + 18432, gth + (size_t)(c0 + row) * 2048 + kc * 128 + f4 * 16);
        }
    };

    fill(0, 0);
    CP_COMMIT();

    if (tid < 128) rinv_s[tid] = g_rinv[n0 + tid];

    const int wm = wid >> 2, wn = wid & 3;
    const int r0w = wm * 64, n0w = wn * 32;
    const int g = lane >> 2, tig = lane & 3;
    const int arow  = (lane & 7) + ((lane >> 3) & 1) * 8;
    const int akoff = (lane >> 4) * 8;
    const int brow  = (lane & 7) + (lane >> 4) * 8;
    const int bkoff = ((lane >> 3) & 1) * 8;

    float acc[4][4][4];
    #pragma unroll
    for (int i = 0; i < 4; ++i)
        #pragma unroll
        for (int j = 0; j < 4; ++j)
            #pragma unroll
            for (int e = 0; e < 4; ++e) acc[i][j][e] = 0.f;

    for (int kc = 0; kc < 16; ++kc) {
        if (kc + 1 < 16) {
            fill(kc + 1, (kc + 1) & 1);
            CP_COMMIT();
            CP_WAIT(1);
        } else {
            CP_WAIT(0);
        }
        __syncthreads();

        const uint32_t Ah_b = sb + G2_BUF + (kc & 1) * G2_BSZ;
        const uint32_t Bh_b = Ah_b + 18432;

        #pragma unroll
        for (int ks = 0; ks < 4; ++ks) {
            uint32_t af[4][4], bf[2][4];
            #pragma unroll
            for (int mt = 0; mt < 4; ++mt) {
                uint32_t off = (uint32_t)((r0w + mt*16 + arow) * 72 + ks*16 + akoff) * 2;
                ldsm4(af[mt], Ah_b + off);
            }
            #pragma unroll
            for (int np = 0; np < 2; ++np) {
                uint32_t off = (uint32_t)((n0w + np*16 + brow) * 72 + ks*16 + bkoff) * 2;
                ldsm4(bf[np], Bh_b + off);
            }
            #pragma unroll
            for (int mt = 0; mt < 4; ++mt)
                #pragma unroll
                for (int ntile = 0; ntile < 4; ++ntile) {
                    int np = ntile >> 1, sub = (ntile & 1) * 2;
                    mma_f16(acc[mt][ntile], af[mt], bf[np][sub], bf[np][sub+1]);
                }
        }
        __syncthreads();
    }

    // ---- epilogue: scale by rinv, stage [t][c] (pad 129), coalesced write ----
    float* stage = reinterpret_cast<float*>(smem + G2_BUF);
    #pragma unroll
    for (int mt = 0; mt < 4; ++mt) {
        int t_lo = r0w + mt*16 + g;
        float rv0 = rinv_s[t_lo], rv1 = rinv_s[t_lo + 8];
        #pragma unroll
        for (int ntile = 0; ntile < 4; ++ntile) {
            int c = n0w + ntile*8 + 2*tig;
            stage[t_lo*129 + c]       = acc[mt][ntile][0] * rv0;
            stage[t_lo*129 + c + 1]   = acc[mt][ntile][1] * rv0;
            stage[(t_lo+8)*129 + c]   = acc[mt][ntile][2] * rv1;
            stage[(t_lo+8)*129 + c+1] = acc[mt][ntile][3] * rv1;
        }
    }
    __syncthreads();
    float* zqb = zq_out + (size_t)bb * CC * TT + t0;
    #pragma unroll 8
    for (int i = tid; i < 16384; i += 256) {
        int c = i >> 7, tt = i & 127;
        zqb[(size_t)(c0 + c) * TT + tt] = stage[tt*129 + c];
    }
}

// ---------------------------------------------------------------------------
extern "C" void kernel_launch(void* const* d_in, const int* in_sizes, int n_in,
                              void* d_out, int out_size) {
    (void)in_sizes; (void)n_in;
    const float* z    = (const float*)d_in[0];
    const float* book = (const float*)d_in[1];
    const float* lpq  = (const float*)d_in[2];
    const float* u    = (const float*)d_in[3];
    float* out = (float*)d_out;

    int full = (out_size >= TOTAL_OUT) ? 1 : 0;
    float* zq   = out;
    float* pq   = full ? (out + ZQ_SIZE)    : nullptr;
    float* prob = full ? (pq + 1)           : nullptr;
    float* logp = full ? (prob + PROB_SIZE) : nullptr;
    float* mean = full ? (logp + PROB_SIZE) : nullptr;

    cudaFuncSetAttribute(gemm1,    cudaFuncAttributeMaxDynamicSharedMemorySize, G1_SMEM);
    cudaFuncSetAttribute(gvq_soft, cudaFuncAttributeMaxDynamicSharedMemorySize, SMB_TOT * (int)sizeof(float));
    cudaFuncSetAttribute(gemm2,    cudaFuncAttributeMaxDynamicSharedMemorySize, G2_SMEM);

    bnorm_kernel<<<128, 256>>>(book);
    split_book<<<256, 256>>>(book);
    gemm1<<<256, 256, G1_SMEM>>>(z, lpq);
    gvq_soft<<<NN/SROWS, 256, SMB_TOT * sizeof(float)>>>(u, lpq, prob, logp, pq, full);
    if (full) {
        mp_reduce1<<<32, 256>>>();
        mp_reduce2<<<4, 256>>>(mean);
    }
    gemm2<<<512, 256, G2_SMEM>>>(zq);
}

// round 16
// speedup vs baseline: 1.1042x; 1.1042x over previous
#include <cuda_runtime.h>
#include <cuda_fp16.h>
#include <cstdint>
#include <math.h>

#define BB   8
#define CC   256
#define TT   4096
#define KK   1024
#define NN   (BB*TT)
#define EPSF 1e-10f

#define ZQ_SIZE   (BB*CC*TT)
#define PROB_SIZE (NN*KK)
#define TOTAL_OUT (ZQ_SIZE + 1 + 2*PROB_SIZE + KK)

#define SROWS 8                       // rows per softmax block (32 KB smem)
#define MPC   64                      // mean-prob reduction partitions

// ---------------- device scratch (static — no runtime allocation) ----------
__device__ float    g_bnorm[KK];
__device__ float    g_mp_partial[(NN/SROWS) * KK];     // 16 MB
__device__ float    g_mp2[MPC * KK];
__device__ float    g_logits[(size_t)NN * KK];         // 128 MB
__device__ uint32_t g_enc_hi[(size_t)NN * KK / 2];     // 64 MB (fp16x2, [n][512w])
__device__ float    g_rinv[NN];
__device__ uint32_t g_book_hi[KK * CC / 2];            // fp16x2 words, [k][128w]
__device__ uint32_t g_book_lo[KK * CC / 2];
__device__ uint32_t g_bookT_hi[CC * KK / 2];           // fp16x2 words, [c][512w]

// ---------------- helpers ---------------------------------------------------
__device__ __forceinline__ uint32_t smem_u32(const void* p) {
    uint32_t a;
    asm("{ .reg .u64 t; cvta.to.shared.u64 t, %1; cvt.u32.u64 %0, t; }"
        : "=r"(a) : "l"(p));
    return a;
}
__device__ __forceinline__ void cp16(uint32_t dst, size_t gsrc) {
    asm volatile("cp.async.cg.shared.global [%0], [%1], 16;" :: "r"(dst), "l"(gsrc));
}
#define CP_COMMIT()  asm volatile("cp.async.commit_group;" ::: "memory")
#define CP_WAIT(N)   asm volatile("cp.async.wait_group %0;" :: "n"(N) : "memory")

__device__ __forceinline__ void ldsm4(uint32_t* r, uint32_t addr) {
    asm volatile("ldmatrix.sync.aligned.m8n8.x4.shared.b16 {%0,%1,%2,%3}, [%4];"
        : "=r"(r[0]), "=r"(r[1]), "=r"(r[2]), "=r"(r[3]) : "r"(addr));
}
__device__ __forceinline__ void mma_f16(float* d, const uint32_t* a,
                                        uint32_t b0, uint32_t b1) {
    asm volatile("mma.sync.aligned.m16n8k16.row.col.f32.f16.f16.f32 "
        "{%0,%1,%2,%3}, {%4,%5,%6,%7}, {%8,%9}, {%0,%1,%2,%3};"
        : "+f"(d[0]), "+f"(d[1]), "+f"(d[2]), "+f"(d[3])
        : "r"(a[0]), "r"(a[1]), "r"(a[2]), "r"(a[3]), "r"(b0), "r"(b1));
}
__device__ __forceinline__ uint32_t pack_h2(float a, float b) {
    __half2 t = __floats2half2_rn(a, b);
    return *reinterpret_cast<uint32_t*>(&t);
}
__device__ __forceinline__ float warp_max(float v) {
    #pragma unroll
    for (int o = 16; o > 0; o >>= 1) v = fmaxf(v, __shfl_xor_sync(0xffffffffu, v, o));
    return v;
}
__device__ __forceinline__ float warp_sum(float v) {
    #pragma unroll
    for (int o = 16; o > 0; o >>= 1) v += __shfl_xor_sync(0xffffffffu, v, o);
    return v;
}
__device__ __forceinline__ float gumbelf(float uu) {
    return -__logf(-__logf(uu + EPSF) + EPSF);
}

// ---------------------------------------------------------------------------
// Prep kernels
// ---------------------------------------------------------------------------
__global__ void bnorm_kernel(const float* __restrict__ book) {
    int gw = (blockIdx.x * blockDim.x + threadIdx.x) >> 5;
    int lane = threadIdx.x & 31;
    if (gw >= KK) return;
    const float* row = book + (size_t)gw * CC;
    float s = 0.f;
    #pragma unroll
    for (int c = lane; c < CC; c += 32) { float v = row[c]; s = fmaf(v, v, s); }
    s = warp_sum(s);
    if (lane == 0) g_bnorm[gw] = s;
}

__global__ void split_book(const float* __restrict__ book) {
    __half* bh  = reinterpret_cast<__half*>(g_book_hi);
    __half* bl  = reinterpret_cast<__half*>(g_book_lo);
    __half* bth = reinterpret_cast<__half*>(g_bookT_hi);
    int idx = blockIdx.x * 256 + threadIdx.x;
    for (int i = idx; i < KK * CC; i += 65536) {
        int k = i >> 8, c = i & 255;
        float v = book[i];
        __half h = __float2half(v);
        bh[i] = h;
        bl[i] = __float2half(v - __half2float(h));
        bth[c * KK + k] = h;
    }
}

// 2-stage deterministic mean_prob reduction — 64 partitions so stage 1 has a
// full-chip grid (65536 threads) instead of a latency-bound 8192-thread one.
__global__ void mp_reduce1() {
    int idx = blockIdx.x * 256 + threadIdx.x;     // 256 blocks -> 65536 threads
    int k = idx & 1023, c = idx >> 10;            // c in 0..63
    const int PB = (NN/SROWS) / MPC;              // 64 partial-blocks per part.
    float s = 0.f;
    #pragma unroll 8
    for (int b = 0; b < PB; ++b)
        s += g_mp_partial[(size_t)(c * PB + b) * KK + k];
    g_mp2[c * KK + k] = s;
}
__global__ void mp_reduce2(float* __restrict__ mean_out) {
    int k = blockIdx.x * 256 + threadIdx.x;
    float s = 0.f;
    #pragma unroll 8
    for (int c = 0; c < MPC; ++c) s += g_mp2[c * KK + k];
    mean_out[k] = s;
}

// ---------------------------------------------------------------------------
// GEMM1 (R10/R13 layout — measured fast): logits = (2*zhi.(bhi+blo) - |zhi|^2 - |b|^2)*pq
// |zhi|^2: per-row additive const -> cancels in all softmax-derived outputs.
// 256 blocks x 256 thr; block = 128 rows; book in 64-code chunks,
// cp.async double-buffered. Warp tile 32x32, ldsm:mma = 6:16.
// ---------------------------------------------------------------------------
#define G1_BBUF  72192
#define G1_BSZ   67584          // per buffer: Bh 33792 + Bl 33792
#define G1_SMEM  207360

__global__ __launch_bounds__(256, 1)
void gemm1(const float* __restrict__ z, const float* __restrict__ lpq) {
    extern __shared__ char smem[];
    float* zn = reinterpret_cast<float*>(smem);
    float* bn = reinterpret_cast<float*>(smem + 512);
    __half* Ah = reinterpret_cast<__half*>(smem + 4608);
    const uint32_t sb = smem_u32(smem);
    const uint32_t Ah_b = sb + 4608;

    const int tid = threadIdx.x, lane = tid & 31, wid = tid >> 5;
    const int blk = blockIdx.x;
    const int n0 = blk * 128;
    const int b  = blk >> 5;
    const int t0 = (blk & 31) * 128;

    const size_t gbh = __cvta_generic_to_global(g_book_hi);
    const size_t gbl = __cvta_generic_to_global(g_book_lo);

    auto fill_b = [&](int nt, int p) {
        const uint32_t dstb = sb + G1_BBUF + p * G1_BSZ;
        const size_t srcoff = (size_t)(nt * 64) * 512;   // 64 rows x 512 B
        #pragma unroll
        for (int j = 0; j < 8; ++j) {
            int i = j * 256 + tid;          // 0..2047
            int row = i >> 5, f4 = i & 31;
            uint32_t d = dstb + row * 528 + f4 * 16;
            size_t s = srcoff + (size_t)row * 512 + f4 * 16;
            cp16(d,         gbh + s);
            cp16(d + 33792, gbl + s);
        }
    };

    fill_b(0, 0);
    CP_COMMIT();

    for (int i = tid; i < KK; i += 256) bn[i] = g_bnorm[i];

    // ---- A fill (hi only): thread = channel c, rows = t ----
    {
        const float* zp = z + (size_t)b * CC * TT + (size_t)tid * TT + t0;
        #pragma unroll 4
        for (int i = 0; i < 32; ++i) {
            float4 v = *reinterpret_cast<const float4*>(zp + 4*i);
            Ah[(4*i+0)*264 + tid] = __float2half(v.x);
            Ah[(4*i+1)*264 + tid] = __float2half(v.y);
            Ah[(4*i+2)*264 + tid] = __float2half(v.z);
            Ah[(4*i+3)*264 + tid] = __float2half(v.w);
        }
    }
    __syncthreads();

    // ---- z row norms from fp16-hi (output-exact by softmax invariance) ----
    for (int rr = 0; rr < 16; ++rr) {
        int r = wid * 16 + rr;
        float s = 0.f;
        #pragma unroll
        for (int c = lane; c < CC; c += 32) {
            float v = __half2float(Ah[r*264 + c]);
            s = fmaf(v, v, s);
        }
        s = warp_sum(s);
        if (lane == 0) zn[r] = s;
    }

    const float pqv = 0.5f / (1.0f + expf(lpq[0]));

    const int wm = wid >> 1, wn = wid & 1;
    const int r0w = wm * 32, n0w = wn * 32;
    const int g = lane >> 2, tig = lane & 3;
    const int arow  = (lane & 7) + ((lane >> 3) & 1) * 8;
    const int akoff = (lane >> 4) * 8;
    const int brow  = (lane & 7) + (lane >> 4) * 8;
    const int bkoff = ((lane >> 3) & 1) * 8;

    for (int nt = 0; nt < 16; ++nt) {
        if (nt + 1 < 16) {
            fill_b(nt + 1, (nt + 1) & 1);
            CP_COMMIT();
            CP_WAIT(1);
        } else {
            CP_WAIT(0);
        }
        __syncthreads();

        const uint32_t Bh_b = sb + G1_BBUF + (nt & 1) * G1_BSZ;
        const uint32_t Bl_b = Bh_b + 33792;

        float acc[2][4][4];
        #pragma unroll
        for (int i = 0; i < 2; ++i)
            #pragma unroll
            for (int j = 0; j < 4; ++j)
                #pragma unroll
                for (int e = 0; e < 4; ++e) acc[i][j][e] = 0.f;

        #pragma unroll 2
        for (int ks = 0; ks < 16; ++ks) {
            uint32_t af[2][4], bf[2][4], blf[2][4];
            #pragma unroll
            for (int mt = 0; mt < 2; ++mt) {
                uint32_t off = (uint32_t)((r0w + mt*16 + arow) * 264 + ks*16 + akoff) * 2;
                ldsm4(af[mt], Ah_b + off);
            }
            #pragma unroll
            for (int np = 0; np < 2; ++np) {
                uint32_t off = (uint32_t)((n0w + np*16 + brow) * 264 + ks*16 + bkoff) * 2;
                ldsm4(bf[np],  Bh_b + off);
                ldsm4(blf[np], Bl_b + off);
            }
            #pragma unroll
            for (int mt = 0; mt < 2; ++mt)
                #pragma unroll
                for (int ntile = 0; ntile < 4; ++ntile) {
                    int np = ntile >> 1, sub = (ntile & 1) * 2;
                    mma_f16(acc[mt][ntile], af[mt], bf[np][sub],  bf[np][sub+1]);
                    mma_f16(acc[mt][ntile], af[mt], blf[np][sub], blf[np][sub+1]);
                }
        }

        // epilogue: scale + direct float2 stores to g_logits
        #pragma unroll
        for (int mt = 0; mt < 2; ++mt) {
            int r_lo = r0w + mt*16 + g;
            float zn0 = zn[r_lo], zn1 = zn[r_lo + 8];
            #pragma unroll
            for (int ntile = 0; ntile < 4; ++ntile) {
                int col = nt*64 + n0w + ntile*8 + 2*tig;
                float bn0 = bn[col], bn1 = bn[col + 1];
                float2 w0, w1;
                w0.x = (2.f*acc[mt][ntile][0] - zn0 - bn0) * pqv;
                w0.y = (2.f*acc[mt][ntile][1] - zn0 - bn1) * pqv;
                w1.x = (2.f*acc[mt][ntile][2] - zn1 - bn0) * pqv;
                w1.y = (2.f*acc[mt][ntile][3] - zn1 - bn1) * pqv;
                *reinterpret_cast<float2*>(&g_logits[(size_t)(n0 + r_lo) * KK + col]) = w0;
                *reinterpret_cast<float2*>(&g_logits[(size_t)(n0 + r_lo + 8) * KK + col]) = w1;
            }
        }
        __syncthreads();
    }
}

// ---------------------------------------------------------------------------
// Softmax kernel: prob/log_prob/mean partials + Gumbel-exp -> enc (fp16 hi)
// 4096 blocks x 256 thr; block = 8 rows; 32 KB smem + <=64 regs -> 4 CTAs/SM
// ---------------------------------------------------------------------------
#define SMB_TOT  (SROWS * KK + 8)

__global__ __launch_bounds__(256, 4)
void gvq_soft(const float* __restrict__ u, const float* __restrict__ lpq,
              float* __restrict__ prob_out, float* __restrict__ logp_out,
              float* __restrict__ pq_out, int full)
{
    extern __shared__ float sm[];
    float* L  = sm;
    float* ra = sm + SROWS * KK;

    const int tid = threadIdx.x, blk = blockIdx.x;
    const int n0 = blk * SROWS;
    const int lane = tid & 31, warp = tid >> 5;

    if (full && blk == 0 && tid == 0)
        *pq_out = 0.5f / (1.0f + expf(lpq[0]));

    #pragma unroll
    for (int it = 0; it < 8; ++it) {
        int idx = it * 256 + tid;
        int r = idx >> 8, kw = idx & 255;
        *reinterpret_cast<float4*>(&L[r * KK + kw * 4]) =
            *reinterpret_cast<const float4*>(&g_logits[(size_t)(n0 + r) * KK + kw * 4]);
    }
    __syncthreads();

    if (full) {
        // warp w handles row w (8 warps, 8 rows)
        {
            int r = warp;
            const float* Lr = L + r * KK;
            float m = __int_as_float(0xff800000);
            #pragma unroll
            for (int kb = 0; kb < 8; ++kb) {
                float4 v = *reinterpret_cast<const float4*>(Lr + kb*128 + lane*4);
                m = fmaxf(m, fmaxf(fmaxf(v.x, v.y), fmaxf(v.z, v.w)));
            }
            m = warp_max(m);
            float s = 0.f;
            #pragma unroll
            for (int kb = 0; kb < 8; ++kb) {
                float4 v = *reinterpret_cast<const float4*>(Lr + kb*128 + lane*4);
                s += __expf(v.x - m) + __expf(v.y - m) + __expf(v.z - m) + __expf(v.w - m);
            }
            s = warp_sum(s);
            if (lane == 0) ra[r] = m + __logf(s);
        }
        __syncthreads();

        const float invN = 1.0f / (float)NN;
        #pragma unroll
        for (int j = 0; j < 4; ++j) {
            int k = tid + j * 256;
            float mp = 0.f;
            #pragma unroll 8
            for (int r = 0; r < SROWS; ++r) {
                float lp = L[r * KK + k] - ra[r];
                float p  = __expf(lp);
                prob_out[(size_t)(n0 + r) * KK + k] = p;
                logp_out[(size_t)(n0 + r) * KK + k] = lp;
                mp += p;
            }
            g_mp_partial[(size_t)blk * KK + k] = mp * invN;
        }
        __syncthreads();
    }

    // Gumbel + temperature-0.5 softmax; emit unnormalized exp as fp16 (hi only)
    {
        int r = warp;
        const float* ur = u + (size_t)(n0 + r) * KK;
        float* Lr = L + r * KK;
        float m = __int_as_float(0xff800000);
        #pragma unroll
        for (int kb = 0; kb < 8; ++kb) {
            float4 uv = *reinterpret_cast<const float4*>(ur + kb*128 + lane*4);
            float4 lv = *reinterpret_cast<float4*>(Lr + kb*128 + lane*4);
            lv.x += gumbelf(uv.x); lv.y += gumbelf(uv.y);
            lv.z += gumbelf(uv.z); lv.w += gumbelf(uv.w);
            *reinterpret_cast<float4*>(Lr + kb*128 + lane*4) = lv;
            m = fmaxf(m, fmaxf(fmaxf(lv.x, lv.y), fmaxf(lv.z, lv.w)));
        }
        m = warp_max(m);
        float s = 0.f;
        #pragma unroll
        for (int kb = 0; kb < 8; ++kb) {
            float4 lv = *reinterpret_cast<float4*>(Lr + kb*128 + lane*4);
            float e0 = __expf(2.0f * (lv.x - m));
            float e1 = __expf(2.0f * (lv.y - m));
            float e2 = __expf(2.0f * (lv.z - m));
            float e3 = __expf(2.0f * (lv.w - m));
            s += e0 + e1 + e2 + e3;
            uint2 hv;
            hv.x = pack_h2(e0, e1);
            hv.y = pack_h2(e2, e3);
            reinterpret_cast<uint2*>(g_enc_hi)[(size_t)(n0 + r) * 256 + kb * 32 + lane] = hv;
        }
        s = warp_sum(s);
        if (lane == 0) g_rinv[n0 + r] = 1.0f / s;
    }
}

// ---------------------------------------------------------------------------
// GEMM2: z_q = (ehi @ bhi) * rinv  (fp16 1-term), cp.async double-buffer
// 512 blocks: blk>>1 = 128-row tile, blk&1 = 128-c half. k streamed in 64s.
// ---------------------------------------------------------------------------
#define G2_BUF   512
#define G2_BSZ   36864
#define G2_SMEM  74240

__global__ __launch_bounds__(256, 2)
void gemm2(float* __restrict__ zq_out) {
    extern __shared__ char smem[];
    float* rinv_s = reinterpret_cast<float*>(smem);
    const uint32_t sb = smem_u32(smem);

    const int tid = threadIdx.x, lane = tid & 31, wid = tid >> 5;
    const int blk = blockIdx.x;
    const int rt = blk >> 1, ch = blk & 1;
    const int n0 = rt * 128;
    const int c0 = ch * 128;
    const int bb = rt >> 5;
    const int t0 = (rt & 31) * 128;

    const size_t geh = __cvta_generic_to_global(g_enc_hi);
    const size_t gth = __cvta_generic_to_global(g_bookT_hi);

    auto fill = [&](int kc, int p) {
        const uint32_t dstb = sb + G2_BUF + p * G2_BSZ;
        #pragma unroll
        for (int j = 0; j < 4; ++j) {
            int i = j * 256 + tid;           // 0..1023
            int row = i >> 3, f4 = i & 7;
            uint32_t d = dstb + row * 144 + f4 * 16;
            cp16(d,         geh + (size_t)(n0 + row) * 2048 + kc * 128 + f4 * 16);
            cp16(d + 18432, gth + (size_t)(c0 + row) * 2048 + kc * 128 + f4 * 16);
        }
    };

    fill(0, 0);
    CP_COMMIT();

    if (tid < 128) rinv_s[tid] = g_rinv[n0 + tid];

    const int wm = wid >> 2, wn = wid & 3;
    const int r0w = wm * 64, n0w = wn * 32;
    const int g = lane >> 2, tig = lane & 3;
    const int arow  = (lane & 7) + ((lane >> 3) & 1) * 8;
    const int akoff = (lane >> 4) * 8;
    const int brow  = (lane & 7) + (lane >> 4) * 8;
    const int bkoff = ((lane >> 3) & 1) * 8;

    float acc[4][4][4];
    #pragma unroll
    for (int i = 0; i < 4; ++i)
        #pragma unroll
        for (int j = 0; j < 4; ++j)
            #pragma unroll
            for (int e = 0; e < 4; ++e) acc[i][j][e] = 0.f;

    for (int kc = 0; kc < 16; ++kc) {
        if (kc + 1 < 16) {
            fill(kc + 1, (kc + 1) & 1);
            CP_COMMIT();
            CP_WAIT(1);
        } else {
            CP_WAIT(0);
        }
        __syncthreads();

        const uint32_t Ah_b = sb + G2_BUF + (kc & 1) * G2_BSZ;
        const uint32_t Bh_b = Ah_b + 18432;

        #pragma unroll
        for (int ks = 0; ks < 4; ++ks) {
            uint32_t af[4][4], bf[2][4];
            #pragma unroll
            for (int mt = 0; mt < 4; ++mt) {
                uint32_t off = (uint32_t)((r0w + mt*16 + arow) * 72 + ks*16 + akoff) * 2;
                ldsm4(af[mt], Ah_b + off);
            }
            #pragma unroll
            for (int np = 0; np < 2; ++np) {
                uint32_t off = (uint32_t)((n0w + np*16 + brow) * 72 + ks*16 + bkoff) * 2;
                ldsm4(bf[np], Bh_b + off);
            }
            #pragma unroll
            for (int mt = 0; mt < 4; ++mt)
                #pragma unroll
                for (int ntile = 0; ntile < 4; ++ntile) {
                    int np = ntile >> 1, sub = (ntile & 1) * 2;
                    mma_f16(acc[mt][ntile], af[mt], bf[np][sub], bf[np][sub+1]);
                }
        }
        __syncthreads();
    }

    // ---- epilogue: scale by rinv, stage [t][c] (pad 129), coalesced write ----
    float* stage = reinterpret_cast<float*>(smem + G2_BUF);
    #pragma unroll
    for (int mt = 0; mt < 4; ++mt) {
        int t_lo = r0w + mt*16 + g;
        float rv0 = rinv_s[t_lo], rv1 = rinv_s[t_lo + 8];
        #pragma unroll
        for (int ntile = 0; ntile < 4; ++ntile) {
            int c = n0w + ntile*8 + 2*tig;
            stage[t_lo*129 + c]       = acc[mt][ntile][0] * rv0;
            stage[t_lo*129 + c + 1]   = acc[mt][ntile][1] * rv0;
            stage[(t_lo+8)*129 + c]   = acc[mt][ntile][2] * rv1;
            stage[(t_lo+8)*129 + c+1] = acc[mt][ntile][3] * rv1;
        }
    }
    __syncthreads();
    float* zqb = zq_out + (size_t)bb * CC * TT + t0;
    #pragma unroll 8
    for (int i = tid; i < 16384; i += 256) {
        int c = i >> 7, tt = i & 127;
        zqb[(size_t)(c0 + c) * TT + tt] = stage[tt*129 + c];
    }
}

// ---------------------------------------------------------------------------
extern "C" void kernel_launch(void* const* d_in, const int* in_sizes, int n_in,
                              void* d_out, int out_size) {
    (void)in_sizes; (void)n_in;
    const float* z    = (const float*)d_in[0];
    const float* book = (const float*)d_in[1];
    const float* lpq  = (const float*)d_in[2];
    const float* u    = (const float*)d_in[3];
    float* out = (float*)d_out;

    int full = (out_size >= TOTAL_OUT) ? 1 : 0;
    float* zq   = out;
    float* pq   = full ? (out + ZQ_SIZE)    : nullptr;
    float* prob = full ? (pq + 1)           : nullptr;
    float* logp = full ? (prob + PROB_SIZE) : nullptr;
    float* mean = full ? (logp + PROB_SIZE) : nullptr;

    cudaFuncSetAttribute(gemm1,    cudaFuncAttributeMaxDynamicSharedMemorySize, G1_SMEM);
    cudaFuncSetAttribute(gvq_soft, cudaFuncAttributeMaxDynamicSharedMemorySize, SMB_TOT * (int)sizeof(float));
    cudaFuncSetAttribute(gemm2,    cudaFuncAttributeMaxDynamicSharedMemorySize, G2_SMEM);

    bnorm_kernel<<<128, 256>>>(book);
    split_book<<<256, 256>>>(book);
    gemm1<<<256, 256, G1_SMEM>>>(z, lpq);
    gvq_soft<<<NN/SROWS, 256, SMB_TOT * sizeof(float)>>>(u, lpq, prob, logp, pq, full);
    if (full) {
        mp_reduce1<<<256, 256>>>();
        mp_reduce2<<<4, 256>>>(mean);
    }
    gemm2<<<512, 256, G2_SMEM>>>(zq);
}

// round 17
// speedup vs baseline: 1.2903x; 1.1686x over previous
#include <cuda_runtime.h>
#include <cuda_fp16.h>
#include <cstdint>
#include <math.h>

#define BB   8
#define CC   256
#define TT   4096
#define KK   1024
#define NN   (BB*TT)
#define EPSF 1e-10f

#define ZQ_SIZE   (BB*CC*TT)
#define PROB_SIZE (NN*KK)
#define TOTAL_OUT (ZQ_SIZE + 1 + 2*PROB_SIZE + KK)

#define SROWS 8                       // rows per softmax block (32 KB smem)
#define MPC   64                      // mean-prob reduction partitions

// ---------------- device scratch (static — no runtime allocation) ----------
__device__ float    g_bnorm[KK];
__device__ float    g_mp_partial[(NN/SROWS) * KK];     // 16 MB
__device__ float    g_mp2[MPC * KK];
__device__ float    g_logits[(size_t)NN * KK];         // 128 MB
__device__ uint32_t g_enc_hi[(size_t)NN * KK / 2];     // 64 MB (fp16x2, [n][512w])
__device__ float    g_rinv[NN];
__device__ uint32_t g_book_hi[KK * CC / 2];            // fp16x2 words, [k][128w]
__device__ uint32_t g_bookT_hi[CC * KK / 2];           // fp16x2 words, [c][512w]

// ---------------- helpers ---------------------------------------------------
__device__ __forceinline__ uint32_t smem_u32(const void* p) {
    uint32_t a;
    asm("{ .reg .u64 t; cvta.to.shared.u64 t, %1; cvt.u32.u64 %0, t; }"
        : "=r"(a) : "l"(p));
    return a;
}
__device__ __forceinline__ void cp16(uint32_t dst, size_t gsrc) {
    asm volatile("cp.async.cg.shared.global [%0], [%1], 16;" :: "r"(dst), "l"(gsrc));
}
#define CP_COMMIT()  asm volatile("cp.async.commit_group;" ::: "memory")
#define CP_WAIT(N)   asm volatile("cp.async.wait_group %0;" :: "n"(N) : "memory")

__device__ __forceinline__ void ldsm4(uint32_t* r, uint32_t addr) {
    asm volatile("ldmatrix.sync.aligned.m8n8.x4.shared.b16 {%0,%1,%2,%3}, [%4];"
        : "=r"(r[0]), "=r"(r[1]), "=r"(r[2]), "=r"(r[3]) : "r"(addr));
}
__device__ __forceinline__ void mma_f16(float* d, const uint32_t* a,
                                        uint32_t b0, uint32_t b1) {
    asm volatile("mma.sync.aligned.m16n8k16.row.col.f32.f16.f16.f32 "
        "{%0,%1,%2,%3}, {%4,%5,%6,%7}, {%8,%9}, {%0,%1,%2,%3};"
        : "+f"(d[0]), "+f"(d[1]), "+f"(d[2]), "+f"(d[3])
        : "r"(a[0]), "r"(a[1]), "r"(a[2]), "r"(a[3]), "r"(b0), "r"(b1));
}
__device__ __forceinline__ uint32_t pack_h2(float a, float b) {
    __half2 t = __floats2half2_rn(a, b);
    return *reinterpret_cast<uint32_t*>(&t);
}
__device__ __forceinline__ float warp_max(float v) {
    #pragma unroll
    for (int o = 16; o > 0; o >>= 1) v = fmaxf(v, __shfl_xor_sync(0xffffffffu, v, o));
    return v;
}
__device__ __forceinline__ float warp_sum(float v) {
    #pragma unroll
    for (int o = 16; o > 0; o >>= 1) v += __shfl_xor_sync(0xffffffffu, v, o);
    return v;
}
__device__ __forceinline__ float gumbelf(float uu) {
    return -__logf(-__logf(uu + EPSF) + EPSF);
}

// ---------------------------------------------------------------------------
// Prep kernels
// ---------------------------------------------------------------------------
__global__ void bnorm_kernel(const float* __restrict__ book) {
    int gw = (blockIdx.x * blockDim.x + threadIdx.x) >> 5;
    int lane = threadIdx.x & 31;
    if (gw >= KK) return;
    const float* row = book + (size_t)gw * CC;
    float s = 0.f;
    #pragma unroll
    for (int c = lane; c < CC; c += 32) { float v = row[c]; s = fmaf(v, v, s); }
    s = warp_sum(s);
    if (lane == 0) g_bnorm[gw] = s;
}

__global__ void split_book(const float* __restrict__ book) {
    __half* bh  = reinterpret_cast<__half*>(g_book_hi);
    __half* bth = reinterpret_cast<__half*>(g_bookT_hi);
    int idx = blockIdx.x * 256 + threadIdx.x;
    for (int i = idx; i < KK * CC; i += 65536) {
        int k = i >> 8, c = i & 255;
        __half h = __float2half(book[i]);
        bh[i] = h;
        bth[c * KK + k] = h;
    }
}

// 2-stage deterministic mean_prob reduction — 64 partitions (full-chip stage 1)
__global__ void mp_reduce1() {
    int idx = blockIdx.x * 256 + threadIdx.x;     // 256 blocks -> 65536 threads
    int k = idx & 1023, c = idx >> 10;            // c in 0..63
    const int PB = (NN/SROWS) / MPC;              // 64 partial-blocks per part.
    float s = 0.f;
    #pragma unroll 8
    for (int b = 0; b < PB; ++b)
        s += g_mp_partial[(size_t)(c * PB + b) * KK + k];
    g_mp2[c * KK + k] = s;
}
__global__ void mp_reduce2(float* __restrict__ mean_out) {
    int k = blockIdx.x * 256 + threadIdx.x;
    float s = 0.f;
    #pragma unroll 8
    for (int c = 0; c < MPC; ++c) s += g_mp2[c * KK + k];
    mean_out[k] = s;
}

// ---------------------------------------------------------------------------
// GEMM1 (fp16 1-term): logits = (2*zhi.bhi - |zhi|^2 - |b|^2)*pq
// |zhi|^2: per-row additive const -> cancels in all softmax-derived outputs.
// Dropped zhi.blo term: ~1.6e-4 logit abs err (measured ladder: ~+1e-4 rel).
// 256 blocks x 256 thr; block = 128 rows; book hi in 64-code chunks,
// cp.async double-buffered. Warp tile 32x32, ldsm:mma = 4:8.
// smem: zn 0..512 | bn 512..4608 | Ah 4608 (67584) | Bbuf[2] @72192 (2x33792)
// ---------------------------------------------------------------------------
#define G1_BBUF  72192
#define G1_BSZ   33792          // per buffer: Bh only
#define G1_SMEM  139776

__global__ __launch_bounds__(256, 1)
void gemm1(const float* __restrict__ z, const float* __restrict__ lpq) {
    extern __shared__ char smem[];
    float* zn = reinterpret_cast<float*>(smem);
    float* bn = reinterpret_cast<float*>(smem + 512);
    __half* Ah = reinterpret_cast<__half*>(smem + 4608);
    const uint32_t sb = smem_u32(smem);
    const uint32_t Ah_b = sb + 4608;

    const int tid = threadIdx.x, lane = tid & 31, wid = tid >> 5;
    const int blk = blockIdx.x;
    const int n0 = blk * 128;
    const int b  = blk >> 5;
    const int t0 = (blk & 31) * 128;

    const size_t gbh = __cvta_generic_to_global(g_book_hi);

    auto fill_b = [&](int nt, int p) {
        const uint32_t dstb = sb + G1_BBUF + p * G1_BSZ;
        const size_t srcoff = (size_t)(nt * 64) * 512;   // 64 rows x 512 B
        #pragma unroll
        for (int j = 0; j < 8; ++j) {
            int i = j * 256 + tid;          // 0..2047
            int row = i >> 5, f4 = i & 31;
            cp16(dstb + row * 528 + f4 * 16,
                 gbh + srcoff + (size_t)row * 512 + f4 * 16);
        }
    };

    fill_b(0, 0);
    CP_COMMIT();

    for (int i = tid; i < KK; i += 256) bn[i] = g_bnorm[i];

    // ---- A fill (hi only): thread = channel c, rows = t ----
    {
        const float* zp = z + (size_t)b * CC * TT + (size_t)tid * TT + t0;
        #pragma unroll 4
        for (int i = 0; i < 32; ++i) {
            float4 v = *reinterpret_cast<const float4*>(zp + 4*i);
            Ah[(4*i+0)*264 + tid] = __float2half(v.x);
            Ah[(4*i+1)*264 + tid] = __float2half(v.y);
            Ah[(4*i+2)*264 + tid] = __float2half(v.z);
            Ah[(4*i+3)*264 + tid] = __float2half(v.w);
        }
    }
    __syncthreads();

    // ---- z row norms from fp16-hi (output-exact by softmax invariance) ----
    for (int rr = 0; rr < 16; ++rr) {
        int r = wid * 16 + rr;
        float s = 0.f;
        #pragma unroll
        for (int c = lane; c < CC; c += 32) {
            float v = __half2float(Ah[r*264 + c]);
            s = fmaf(v, v, s);
        }
        s = warp_sum(s);
        if (lane == 0) zn[r] = s;
    }

    const float pqv = 0.5f / (1.0f + expf(lpq[0]));

    const int wm = wid >> 1, wn = wid & 1;
    const int r0w = wm * 32, n0w = wn * 32;
    const int g = lane >> 2, tig = lane & 3;
    const int arow  = (lane & 7) + ((lane >> 3) & 1) * 8;
    const int akoff = (lane >> 4) * 8;
    const int brow  = (lane & 7) + (lane >> 4) * 8;
    const int bkoff = ((lane >> 3) & 1) * 8;

    for (int nt = 0; nt < 16; ++nt) {
        if (nt + 1 < 16) {
            fill_b(nt + 1, (nt + 1) & 1);
            CP_COMMIT();
            CP_WAIT(1);
        } else {
            CP_WAIT(0);
        }
        __syncthreads();

        const uint32_t Bh_b = sb + G1_BBUF + (nt & 1) * G1_BSZ;

        float acc[2][4][4];
        #pragma unroll
        for (int i = 0; i < 2; ++i)
            #pragma unroll
            for (int j = 0; j < 4; ++j)
                #pragma unroll
                for (int e = 0; e < 4; ++e) acc[i][j][e] = 0.f;

        #pragma unroll 2
        for (int ks = 0; ks < 16; ++ks) {
            uint32_t af[2][4], bf[2][4];
            #pragma unroll
            for (int mt = 0; mt < 2; ++mt) {
                uint32_t off = (uint32_t)((r0w + mt*16 + arow) * 264 + ks*16 + akoff) * 2;
                ldsm4(af[mt], Ah_b + off);
            }
            #pragma unroll
            for (int np = 0; np < 2; ++np) {
                uint32_t off = (uint32_t)((n0w + np*16 + brow) * 264 + ks*16 + bkoff) * 2;
                ldsm4(bf[np], Bh_b + off);
            }
            #pragma unroll
            for (int mt = 0; mt < 2; ++mt)
                #pragma unroll
                for (int ntile = 0; ntile < 4; ++ntile) {
                    int np = ntile >> 1, sub = (ntile & 1) * 2;
                    mma_f16(acc[mt][ntile], af[mt], bf[np][sub], bf[np][sub+1]);
                }
        }

        // epilogue: scale + direct float2 stores to g_logits
        #pragma unroll
        for (int mt = 0; mt < 2; ++mt) {
            int r_lo = r0w + mt*16 + g;
            float zn0 = zn[r_lo], zn1 = zn[r_lo + 8];
            #pragma unroll
            for (int ntile = 0; ntile < 4; ++ntile) {
                int col = nt*64 + n0w + ntile*8 + 2*tig;
                float bn0 = bn[col], bn1 = bn[col + 1];
                float2 w0, w1;
                w0.x = (2.f*acc[mt][ntile][0] - zn0 - bn0) * pqv;
                w0.y = (2.f*acc[mt][ntile][1] - zn0 - bn1) * pqv;
                w1.x = (2.f*acc[mt][ntile][2] - zn1 - bn0) * pqv;
                w1.y = (2.f*acc[mt][ntile][3] - zn1 - bn1) * pqv;
                *reinterpret_cast<float2*>(&g_logits[(size_t)(n0 + r_lo) * KK + col]) = w0;
                *reinterpret_cast<float2*>(&g_logits[(size_t)(n0 + r_lo + 8) * KK + col]) = w1;
            }
        }
        __syncthreads();
    }
}

// ---------------------------------------------------------------------------
// Softmax kernel: prob/log_prob/mean partials + Gumbel-exp -> enc (fp16 hi)
// 4096 blocks x 256 thr; block = 8 rows; 32 KB smem + <=64 regs -> 4 CTAs/SM
// ---------------------------------------------------------------------------
#define SMB_TOT  (SROWS * KK + 8)

__global__ __launch_bounds__(256, 4)
void gvq_soft(const float* __restrict__ u, const float* __restrict__ lpq,
              float* __restrict__ prob_out, float* __restrict__ logp_out,
              float* __restrict__ pq_out, int full)
{
    extern __shared__ float sm[];
    float* L  = sm;
    float* ra = sm + SROWS * KK;

    const int tid = threadIdx.x, blk = blockIdx.x;
    const int n0 = blk * SROWS;
    const int lane = tid & 31, warp = tid >> 5;

    if (full && blk == 0 && tid == 0)
        *pq_out = 0.5f / (1.0f + expf(lpq[0]));

    #pragma unroll
    for (int it = 0; it < 8; ++it) {
        int idx = it * 256 + tid;
        int r = idx >> 8, kw = idx & 255;
        *reinterpret_cast<float4*>(&L[r * KK + kw * 4]) =
            *reinterpret_cast<const float4*>(&g_logits[(size_t)(n0 + r) * KK + kw * 4]);
    }
    __syncthreads();

    if (full) {
        // warp w handles row w (8 warps, 8 rows)
        {
            int r = warp;
            const float* Lr = L + r * KK;
            float m = __int_as_float(0xff800000);
            #pragma unroll
            for (int kb = 0; kb < 8; ++kb) {
                float4 v = *reinterpret_cast<const float4*>(Lr + kb*128 + lane*4);
                m = fmaxf(m, fmaxf(fmaxf(v.x, v.y), fmaxf(v.z, v.w)));
            }
            m = warp_max(m);
            float s = 0.f;
            #pragma unroll
            for (int kb = 0; kb < 8; ++kb) {
                float4 v = *reinterpret_cast<const float4*>(Lr + kb*128 + lane*4);
                s += __expf(v.x - m) + __expf(v.y - m) + __expf(v.z - m) + __expf(v.w - m);
            }
            s = warp_sum(s);
            if (lane == 0) ra[r] = m + __logf(s);
        }
        __syncthreads();

        const float invN = 1.0f / (float)NN;
        #pragma unroll
        for (int j = 0; j < 4; ++j) {
            int k = tid + j * 256;
            float mp = 0.f;
            #pragma unroll 8
            for (int r = 0; r < SROWS; ++r) {
                float lp = L[r * KK + k] - ra[r];
                float p  = __expf(lp);
                prob_out[(size_t)(n0 + r) * KK + k] = p;
                logp_out[(size_t)(n0 + r) * KK + k] = lp;
                mp += p;
            }
            g_mp_partial[(size_t)blk * KK + k] = mp * invN;
        }
        __syncthreads();
    }

    // Gumbel + temperature-0.5 softmax; emit unnormalized exp as fp16 (hi only)
    {
        int r = warp;
        const float* ur = u + (size_t)(n0 + r) * KK;
        float* Lr = L + r * KK;
        float m = __int_as_float(0xff800000);
        #pragma unroll
        for (int kb = 0; kb < 8; ++kb) {
            float4 uv = *reinterpret_cast<const float4*>(ur + kb*128 + lane*4);
            float4 lv = *reinterpret_cast<float4*>(Lr + kb*128 + lane*4);
            lv.x += gumbelf(uv.x); lv.y += gumbelf(uv.y);
            lv.z += gumbelf(uv.z); lv.w += gumbelf(uv.w);
            *reinterpret_cast<float4*>(Lr + kb*128 + lane*4) = lv;
            m = fmaxf(m, fmaxf(fmaxf(lv.x, lv.y), fmaxf(lv.z, lv.w)));
        }
        m = warp_max(m);
        float s = 0.f;
        #pragma unroll
        for (int kb = 0; kb < 8; ++kb) {
            float4 lv = *reinterpret_cast<float4*>(Lr + kb*128 + lane*4);
            float e0 = __expf(2.0f * (lv.x - m));
            float e1 = __expf(2.0f * (lv.y - m));
            float e2 = __expf(2.0f * (lv.z - m));
            float e3 = __expf(2.0f * (lv.w - m));
            s += e0 + e1 + e2 + e3;
            uint2 hv;
            hv.x = pack_h2(e0, e1);
            hv.y = pack_h2(e2, e3);
            reinterpret_cast<uint2*>(g_enc_hi)[(size_t)(n0 + r) * 256 + kb * 32 + lane] = hv;
        }
        s = warp_sum(s);
        if (lane == 0) g_rinv[n0 + r] = 1.0f / s;
    }
}

// ---------------------------------------------------------------------------
// GEMM2: z_q = (ehi @ bhi) * rinv  (fp16 1-term), cp.async double-buffer
// 512 blocks: blk>>1 = 128-row tile, blk&1 = 128-c half. k streamed in 64s.
// ---------------------------------------------------------------------------
#define G2_BUF   512
#define G2_BSZ   36864
#define G2_SMEM  74240

__global__ __launch_bounds__(256, 2)
void gemm2(float* __restrict__ zq_out) {
    extern __shared__ char smem[];
    float* rinv_s = reinterpret_cast<float*>(smem);
    const uint32_t sb = smem_u32(smem);

    const int tid = threadIdx.x, lane = tid & 31, wid = tid >> 5;
    const int blk = blockIdx.x;
    const int rt = blk >> 1, ch = blk & 1;
    const int n0 = rt * 128;
    const int c0 = ch * 128;
    const int bb = rt >> 5;
    const int t0 = (rt & 31) * 128;

    const size_t geh = __cvta_generic_to_global(g_enc_hi);
    const size_t gth = __cvta_generic_to_global(g_bookT_hi);

    auto fill = [&](int kc, int p) {
        const uint32_t dstb = sb + G2_BUF + p * G2_BSZ;
        #pragma unroll
        for (int j = 0; j < 4; ++j) {
            int i = j * 256 + tid;           // 0..1023
            int row = i >> 3, f4 = i & 7;
            uint32_t d = dstb + row * 144 + f4 * 16;
            cp16(d,         geh + (size_t)(n0 + row) * 2048 + kc * 128 + f4 * 16);
            cp16(d + 18432, gth + (size_t)(c0 + row) * 2048 + kc * 128 + f4 * 16);
        }
    };

    fill(0, 0);
    CP_COMMIT();

    if (tid < 128) rinv_s[tid] = g_rinv[n0 + tid];

    const int wm = wid >> 2, wn = wid & 3;
    const int r0w = wm * 64, n0w = wn * 32;
    const int g = lane >> 2, tig = lane & 3;
    const int arow  = (lane & 7) + ((lane >> 3) & 1) * 8;
    const int akoff = (lane >> 4) * 8;
    const int brow  = (lane & 7) + (lane >> 4) * 8;
    const int bkoff = ((lane >> 3) & 1) * 8;

    float acc[4][4][4];
    #pragma unroll
    for (int i = 0; i < 4; ++i)
        #pragma unroll
        for (int j = 0; j < 4; ++j)
            #pragma unroll
            for (int e = 0; e < 4; ++e) acc[i][j][e] = 0.f;

    for (int kc = 0; kc < 16; ++kc) {
        if (kc + 1 < 16) {
            fill(kc + 1, (kc + 1) & 1);
            CP_COMMIT();
            CP_WAIT(1);
        } else {
            CP_WAIT(0);
        }
        __syncthreads();

        const uint32_t Ah_b = sb + G2_BUF + (kc & 1) * G2_BSZ;
        const uint32_t Bh_b = Ah_b + 18432;

        #pragma unroll
        for (int ks = 0; ks < 4; ++ks) {
            uint32_t af[4][4], bf[2][4];
            #pragma unroll
            for (int mt = 0; mt < 4; ++mt) {
                uint32_t off = (uint32_t)((r0w + mt*16 + arow) * 72 + ks*16 + akoff) * 2;
                ldsm4(af[mt], Ah_b + off);
            }
            #pragma unroll
            for (int np = 0; np < 2; ++np) {
                uint32_t off = (uint32_t)((n0w + np*16 + brow) * 72 + ks*16 + bkoff) * 2;
                ldsm4(bf[np], Bh_b + off);
            }
            #pragma unroll
            for (int mt = 0; mt < 4; ++mt)
                #pragma unroll
                for (int ntile = 0; ntile < 4; ++ntile) {
                    int np = ntile >> 1, sub = (ntile & 1) * 2;
                    mma_f16(acc[mt][ntile], af[mt], bf[np][sub], bf[np][sub+1]);
                }
        }
        __syncthreads();
    }

    // ---- epilogue: scale by rinv, stage [t][c] (pad 129), coalesced write ----
    float* stage = reinterpret_cast<float*>(smem + G2_BUF);
    #pragma unroll
    for (int mt = 0; mt < 4; ++mt) {
        int t_lo = r0w + mt*16 + g;
        float rv0 = rinv_s[t_lo], rv1 = rinv_s[t_lo + 8];
        #pragma unroll
        for (int ntile = 0; ntile < 4; ++ntile) {
            int c = n0w + ntile*8 + 2*tig;
            stage[t_lo*129 + c]       = acc[mt][ntile][0] * rv0;
            stage[t_lo*129 + c + 1]   = acc[mt][ntile][1] * rv0;
            stage[(t_lo+8)*129 + c]   = acc[mt][ntile][2] * rv1;
            stage[(t_lo+8)*129 + c+1] = acc[mt][ntile][3] * rv1;
        }
    }
    __syncthreads();
    float* zqb = zq_out + (size_t)bb * CC * TT + t0;
    #pragma unroll 8
    for (int i = tid; i < 16384; i += 256) {
        int c = i >> 7, tt = i & 127;
        zqb[(size_t)(c0 + c) * TT + tt] = stage[tt*129 + c];
    }
}

// ---------------------------------------------------------------------------
extern "C" void kernel_launch(void* const* d_in, const int* in_sizes, int n_in,
                              void* d_out, int out_size) {
    (void)in_sizes; (void)n_in;
    const float* z    = (const float*)d_in[0];
    const float* book = (const float*)d_in[1];
    const float* lpq  = (const float*)d_in[2];
    const float* u    = (const float*)d_in[3];
    float* out = (float*)d_out;

    int full = (out_size >= TOTAL_OUT) ? 1 : 0;
    float* zq   = out;
    float* pq   = full ? (out + ZQ_SIZE)    : nullptr;
    float* prob = full ? (pq + 1)           : nullptr;
    float* logp = full ? (prob + PROB_SIZE) : nullptr;
    float* mean = full ? (logp + PROB_SIZE) : nullptr;

    cudaFuncSetAttribute(gemm1,    cudaFuncAttributeMaxDynamicSharedMemorySize, G1_SMEM);
    cudaFuncSetAttribute(gvq_soft, cudaFuncAttributeMaxDynamicSharedMemorySize, SMB_TOT * (int)sizeof(float));
    cudaFuncSetAttribute(gemm2,    cudaFuncAttributeMaxDynamicSharedMemorySize, G2_SMEM);

    bnorm_kernel<<<128, 256>>>(book);
    split_book<<<256, 256>>>(book);
    gemm1<<<256, 256, G1_SMEM>>>(z, lpq);
    gvq_soft<<<NN/SROWS, 256, SMB_TOT * sizeof(float)>>>(u, lpq, prob, logp, pq, full);
    if (full) {
        mp_reduce1<<<256, 256>>>();
        mp_reduce2<<<4, 256>>>(mean);
    }
    gemm2<<<512, 256, G2_SMEM>>>(zq);
}